// round 7
// baseline (speedup 1.0000x reference)
#include <cuda_runtime.h>

#define NN 512   // nodes
#define NE 512   // edges
#define D  128   // emb dim
#define H  256   // hidden
#define NI 8192  // incidences
#define GRID 148
#define TPB  256

// ---------------- scratch (no allocations allowed) ----------------
__device__ float g_eSum[NE * D];
__device__ float g_eCnt[NE];
__device__ float g_hX [NN * H];
__device__ float g_hEb[NE * H];
__device__ int   g_mode;                 // 1 = indices are int64, 0 = int32
__device__ unsigned g_barCnt = 0;        // grid barrier arrivals
__device__ unsigned g_barGen = 0;        // grid barrier generation (monotonic)

typedef unsigned long long ull;

// fused triad on packed f32x2: acc += relu(x + e) * w
// (no max.f32x2 in PTX: unpack/max/pack — the movs coalesce in SASS)
__device__ __forceinline__ void triad(ull& acc, ull x, ull e, ull w) {
    asm("{\n\t"
        ".reg .f32 lo, hi;\n\t"
        ".reg .b64 t;\n\t"
        "add.rn.f32x2 t, %1, %2;\n\t"
        "mov.b64 {lo, hi}, t;\n\t"
        "max.f32 lo, lo, 0f00000000;\n\t"
        "max.f32 hi, hi, 0f00000000;\n\t"
        "mov.b64 t, {lo, hi};\n\t"
        "fma.rn.f32x2 %0, t, %3, %0;\n\t"
        "}"
        : "+l"(acc) : "l"(x), "l"(e), "l"(w));
}
__device__ __forceinline__ float hsum2(ull t) {
    float lo, hi;
    asm("mov.b64 {%0, %1}, %2;" : "=f"(lo), "=f"(hi) : "l"(t));
    return lo + hi;
}

// sense-reversing grid barrier; generation is monotonic so it is safe across
// graph replays. All GRID CTAs are resident (grid == 148 == #SMs, 1 CTA/SM).
__device__ __forceinline__ void gridBarrier() {
    __syncthreads();
    if (threadIdx.x == 0) {
        __threadfence();
        unsigned gen = *(volatile unsigned*)&g_barGen;
        unsigned my = atomicAdd(&g_barCnt, 1);
        if (my == gridDim.x - 1) {
            g_barCnt = 0;
            __threadfence();
            *(volatile unsigned*)&g_barGen = gen + 1;
        } else {
            while (*(volatile unsigned*)&g_barGen == gen) __nanosleep(32);
        }
        __threadfence();
    }
    __syncthreads();
}

// shared memory reused across phases
// epi:  sE 64*68 | sX 32*66 | sW 64     (26.1 KB)
// gemm: sA 32*36 | sB 32*68             (13.3 KB)
__shared__ float s_mem[64 * 68 + 32 * 66 + 64];

__global__ void __launch_bounds__(TPB) mega(
    const float* __restrict__ X, const void* __restrict__ Vp,
    const void* __restrict__ Ep, const float* __restrict__ W1,
    const float* __restrict__ b1, const float* __restrict__ W2,
    const float* __restrict__ b2, float* __restrict__ out)
{
    int tid = threadIdx.x;
    int bid = blockIdx.x;
    int gtid = bid * TPB + tid;
    const int gsz = GRID * TPB;          // 37888

    // ================= phase 0: zero eSum/eCnt + detect dtype =================
    {
        float4 z = make_float4(0.f, 0.f, 0.f, 0.f);
        for (int i = gtid; i < 16512; i += gsz) {
            if (i < 16384) ((float4*)g_eSum)[i] = z;
            else           ((float4*)g_eCnt)[i - 16384] = z;
        }
        if (gtid == 0) {
            const long long* e64 = (const long long*)Ep;
            int ok = 1;
            #pragma unroll 1
            for (int k = 0; k < 32; k++) {
                long long v = e64[k];
                if (v < 0 || v >= (long long)NE) { ok = 0; break; }
            }
            g_mode = ok;
        }
    }
    gridBarrier();

    // ================= phase 1: scatter-sum + counts (vector RED) =============
    {
        int mode = g_mode;
        if (mode) {
            for (int u = gtid; u < NI * 32; u += gsz) {
                int inc = u >> 5, q = u & 31;
                int v = (int)((const long long*)Vp)[inc];
                int e = (int)((const long long*)Ep)[inc];
                float4 f = *(const float4*)(X + v * D + q * 4);
                float* dst = g_eSum + e * D + q * 4;
                asm volatile("red.global.add.v4.f32 [%0], {%1, %2, %3, %4};"
                             :: "l"(dst), "f"(f.x), "f"(f.y), "f"(f.z), "f"(f.w) : "memory");
                if (q == 0)
                    asm volatile("red.global.add.f32 [%0], %1;"
                                 :: "l"(&g_eCnt[e]), "f"(1.0f) : "memory");
            }
        } else {
            for (int u = gtid; u < NI * 32; u += gsz) {
                int inc = u >> 5, q = u & 31;
                int v = ((const int*)Vp)[inc];
                int e = ((const int*)Ep)[inc];
                float4 f = *(const float4*)(X + v * D + q * 4);
                float* dst = g_eSum + e * D + q * 4;
                asm volatile("red.global.add.v4.f32 [%0], {%1, %2, %3, %4};"
                             :: "l"(dst), "f"(f.x), "f"(f.y), "f"(f.z), "f"(f.w) : "memory");
                if (q == 0)
                    asm volatile("red.global.add.f32 [%0], %1;"
                                 :: "l"(&g_eCnt[e]), "f"(1.0f) : "memory");
            }
        }
    }
    gridBarrier();

    // ================= phase 2: GEMM (128 jobs, one per CTA) ==================
    // job: h0 = (bid&3)*64, r0 = (bid>>2)*32; rows<512 -> hX, else -> hEb (+b1)
    if (bid < 128) {
        float* sA = s_mem;               // 32*36 [k][row]
        float* sB = s_mem + 32 * 36;     // 32*68 [k][h]
        int tx = tid & 15, ty = tid >> 4;
        int h0 = (bid & 3) * 64;
        int r0 = (bid >> 2) * 32;
        bool isX = (r0 < NN);
        int koff = isX ? 0 : D;

        float acc[2][4];
        #pragma unroll
        for (int i = 0; i < 2; i++)
            #pragma unroll
            for (int j = 0; j < 4; j++) acc[i][j] = 0.0f;

        for (int k0 = 0; k0 < D; k0 += 32) {
            __syncthreads();
            {   // A: 32 rows x 32 k = 256 float4
                int kq = tid & 7;
                int r  = tid >> 3;
                int gr = r0 + r;
                float4 f;
                if (isX) {
                    f = *(const float4*)(X + gr * D + k0 + kq * 4);
                } else {
                    f = *(const float4*)(g_eSum + (gr - NN) * D + k0 + kq * 4);
                    float c = g_eCnt[gr - NN];
                    float s = 1.0f / fmaxf(c, 1.0f);
                    f.x *= s; f.y *= s; f.z *= s; f.w *= s;
                }
                sA[(kq * 4 + 0) * 36 + r] = f.x;
                sA[(kq * 4 + 1) * 36 + r] = f.y;
                sA[(kq * 4 + 2) * 36 + r] = f.z;
                sA[(kq * 4 + 3) * 36 + r] = f.w;
            }
            #pragma unroll
            for (int i = 0; i < 2; i++) {  // B: 64 h x 32 k = 512 float4
                int lin = tid + 256 * i;
                int kq = lin & 7;
                int hr = lin >> 3;
                float4 g = *(const float4*)(W1 + (h0 + hr) * (2 * D) + koff + k0 + kq * 4);
                sB[(kq * 4 + 0) * 68 + hr] = g.x;
                sB[(kq * 4 + 1) * 68 + hr] = g.y;
                sB[(kq * 4 + 2) * 68 + hr] = g.z;
                sB[(kq * 4 + 3) * 68 + hr] = g.w;
            }
            __syncthreads();

            #pragma unroll
            for (int kk = 0; kk < 32; kk++) {
                float2 a2 = *(float2*)&sA[kk * 36 + 2 * ty];
                float4 b4 = *(float4*)&sB[kk * 68 + 4 * tx];
                float a[2] = {a2.x, a2.y};
                float b[4] = {b4.x, b4.y, b4.z, b4.w};
                #pragma unroll
                for (int i = 0; i < 2; i++)
                    #pragma unroll
                    for (int j = 0; j < 4; j++)
                        acc[i][j] = fmaf(a[i], b[j], acc[i][j]);
            }
        }

        #pragma unroll
        for (int i = 0; i < 2; i++) {
            int gr = r0 + 2 * ty + i;
            #pragma unroll
            for (int j = 0; j < 4; j++) {
                int h = h0 + 4 * tx + j;
                if (isX) g_hX[gr * H + h] = acc[i][j];
                else     g_hEb[(gr - NN) * H + h] = acc[i][j] + b1[h];
            }
        }
    }
    gridBarrier();

    // ================= phase 3: epilogue (128 jobs, one per CTA) ==============
    // tile 32n x 64m, full h in 4 chunks of 64; thread tile 2n x 4m;
    // direct sigmoid + clip + coalesced store (smem transpose).
    if (bid < 128) {
        float* sE = s_mem;                          // 64*68 [m][h-chunk]
        float* sX = s_mem + 64 * 68;                // 32*66 [n][h-chunk]
        float* sW = s_mem + 64 * 68 + 32 * 66;      // 64
        int ty = tid & 15;                          // n lane
        int tx = tid >> 4;                          // m lane
        int m0 = (bid & 7) * 64;
        int n0 = (bid >> 3) * 32;

        ull acc[2][4];
        #pragma unroll
        for (int i = 0; i < 2; i++)
            #pragma unroll
            for (int j = 0; j < 4; j++) acc[i][j] = 0ULL;

        int xoff[2], eoff[4];
        #pragma unroll
        for (int i = 0; i < 2; i++) xoff[i] = (ty + 16 * i) * 66;
        #pragma unroll
        for (int j = 0; j < 4; j++) eoff[j] = (tx + 16 * j) * 68;

        float4 pX[2], pE[4], pW;

        #define GLOAD(hc)                                                            \
            do {                                                                     \
                _Pragma("unroll")                                                    \
                for (int i_ = 0; i_ < 2; i_++) {                                     \
                    int lin = tid + 256 * i_;                                        \
                    int q = lin & 15, r = lin >> 4;                                  \
                    pX[i_] = *(const float4*)(g_hX + (n0 + r) * H + (hc) + 4 * q);   \
                }                                                                    \
                _Pragma("unroll")                                                    \
                for (int i_ = 0; i_ < 4; i_++) {                                     \
                    int lin = tid + 256 * i_;                                        \
                    int q = lin & 15, r = lin >> 4;                                  \
                    pE[i_] = *(const float4*)(g_hEb + (m0 + r) * H + (hc) + 4 * q);  \
                }                                                                    \
                if (tid < 16) pW = *(const float4*)(W2 + (hc) + 4 * tid);            \
            } while (0)

        #define GSTORE()                                                             \
            do {                                                                     \
                _Pragma("unroll")                                                    \
                for (int i_ = 0; i_ < 2; i_++) {                                     \
                    int lin = tid + 256 * i_;                                        \
                    int q = lin & 15, r = lin >> 4;                                  \
                    *(float2*)&sX[r * 66 + 4 * q]     = make_float2(pX[i_].x, pX[i_].y); \
                    *(float2*)&sX[r * 66 + 4 * q + 2] = make_float2(pX[i_].z, pX[i_].w); \
                }                                                                    \
                _Pragma("unroll")                                                    \
                for (int i_ = 0; i_ < 4; i_++) {                                     \
                    int lin = tid + 256 * i_;                                        \
                    int q = lin & 15, r = lin >> 4;                                  \
                    *(float4*)&sE[r * 68 + 4 * q] = pE[i_];                          \
                }                                                                    \
                if (tid < 16) *(float4*)&sW[4 * tid] = pW;                           \
            } while (0)

        ulonglong2 Wb[2], Eb[2][4];
        ull Xb[2][2][2];
        #define LOADI(s, h)                                                          \
            do {                                                                     \
                Wb[s] = *(const ulonglong2*)&sW[(h)];                                \
                _Pragma("unroll")                                                    \
                for (int i_ = 0; i_ < 2; i_++) {                                     \
                    Xb[s][i_][0] = *(const ull*)&sX[xoff[i_] + (h)];                 \
                    Xb[s][i_][1] = *(const ull*)&sX[xoff[i_] + (h) + 2];             \
                }                                                                    \
                _Pragma("unroll")                                                    \
                for (int j_ = 0; j_ < 4; j_++)                                       \
                    Eb[s][j_] = *(const ulonglong2*)&sE[eoff[j_] + (h)];             \
            } while (0)
        #define COMP(s)                                                              \
            do {                                                                     \
                _Pragma("unroll")                                                    \
                for (int i_ = 0; i_ < 2; i_++)                                       \
                    _Pragma("unroll")                                                \
                    for (int j_ = 0; j_ < 4; j_++) {                                 \
                        triad(acc[i_][j_], Xb[s][i_][0], Eb[s][j_].x, Wb[s].x);      \
                        triad(acc[i_][j_], Xb[s][i_][1], Eb[s][j_].y, Wb[s].y);      \
                    }                                                                \
            } while (0)

        GLOAD(0);
        GSTORE();
        __syncthreads();

        #pragma unroll 1
        for (int c = 0; c < 4; c++) {
            if (c < 3) GLOAD(64 * (c + 1));       // prefetch next chunk
            LOADI(0, 0);
            #pragma unroll
            for (int it = 0; it < 16; it++) {
                if (it < 15) {
                    if (it & 1) LOADI(0, 4 * (it + 1));
                    else        LOADI(1, 4 * (it + 1));
                }
                if (it & 1) COMP(1);
                else        COMP(0);
            }
            if (c < 3) {
                __syncthreads();
                GSTORE();
                __syncthreads();
            }
        }
        #undef GLOAD
        #undef GSTORE
        #undef LOADI
        #undef COMP

        // transpose logits via smem so stores are coalesced float4
        __syncthreads();
        #pragma unroll
        for (int i = 0; i < 2; i++)
            #pragma unroll
            for (int j = 0; j < 4; j++)
                sE[(ty + 16 * i) * 68 + tx + 16 * j] = hsum2(acc[i][j]);
        __syncthreads();

        float b2v = b2[0];
        #pragma unroll
        for (int i = 0; i < 2; i++) {
            int lin = tid + 256 * i;
            int q = lin & 15, r = lin >> 4;       // r: 0..31
            float4 lg = *(float4*)&sE[r * 68 + 4 * q];
            float4 p;
            p.x = 1.0f / (1.0f + __expf(-(lg.x + b2v)));
            p.y = 1.0f / (1.0f + __expf(-(lg.y + b2v)));
            p.z = 1.0f / (1.0f + __expf(-(lg.z + b2v)));
            p.w = 1.0f / (1.0f + __expf(-(lg.w + b2v)));
            p.x = fminf(fmaxf(p.x, 1e-6f), 1.0f - 1e-6f);
            p.y = fminf(fmaxf(p.y, 1e-6f), 1.0f - 1e-6f);
            p.z = fminf(fmaxf(p.z, 1e-6f), 1.0f - 1e-6f);
            p.w = fminf(fmaxf(p.w, 1e-6f), 1.0f - 1e-6f);
            *(float4*)(out + (n0 + r) * NE + m0 + 4 * q) = p;
        }
    }
}

// ---------------- launch ----------------
extern "C" void kernel_launch(void* const* d_in, const int* in_sizes, int n_in,
                              void* d_out, int out_size) {
    const float* X  = (const float*)d_in[0];
    const void*  V  = d_in[1];
    const void*  E  = d_in[2];
    const float* W1 = (const float*)d_in[3];
    const float* b1 = (const float*)d_in[4];
    const float* W2 = (const float*)d_in[5];
    const float* b2 = (const float*)d_in[6];
    float* out = (float*)d_out;

    mega<<<GRID, TPB>>>(X, V, E, W1, b1, W2, b2, out);
}

// round 8
// speedup vs baseline: 1.1497x; 1.1497x over previous
#include <cuda_runtime.h>

#define NN 512   // nodes
#define NE 512   // edges
#define D  128   // emb dim
#define H  256   // hidden
#define NI 8192  // incidences

// ---------------- scratch (no allocations allowed) ----------------
__device__ float g_eSum[NE * D];
__device__ float g_eCnt[NE];
__device__ float g_hX [NN * H];
__device__ float g_hEb[NE * H];
__device__ int   g_mode;   // 1 = indices are int64, 0 = int32

typedef unsigned long long ull;

// fused triad on packed f32x2: acc += relu(x + e) * w
__device__ __forceinline__ void triad(ull& acc, ull x, ull e, ull w) {
    asm("{\n\t"
        ".reg .f32 lo, hi;\n\t"
        ".reg .b64 t;\n\t"
        "add.rn.f32x2 t, %1, %2;\n\t"
        "mov.b64 {lo, hi}, t;\n\t"
        "max.f32 lo, lo, 0f00000000;\n\t"
        "max.f32 hi, hi, 0f00000000;\n\t"
        "mov.b64 t, {lo, hi};\n\t"
        "fma.rn.f32x2 %0, t, %3, %0;\n\t"
        "}"
        : "+l"(acc) : "l"(x), "l"(e), "l"(w));
}
__device__ __forceinline__ float hsum2(ull t) {
    float lo, hi;
    asm("mov.b64 {%0, %1}, %2;" : "=f"(lo), "=f"(hi) : "l"(t));
    return lo + hi;
}

// ---------------- K0: zero scratch + detect index dtype ----------------
__global__ void k_zero_detect(const void* __restrict__ Ep) {
    int i = blockIdx.x * 256 + threadIdx.x;          // 65*256 covers 16512 float4
    float4 z = make_float4(0.f, 0.f, 0.f, 0.f);
    if (i < 16384) {
        ((float4*)g_eSum)[i] = z;
    } else if (i < 16512) {
        ((float4*)g_eCnt)[i - 16384] = z;
    }
    if (blockIdx.x == 0 && threadIdx.x == 0) {
        const long long* e64 = (const long long*)Ep;
        int ok = 1;
        #pragma unroll 1
        for (int k = 0; k < 32; k++) {
            long long v = e64[k];
            if (v < 0 || v >= (long long)NE) { ok = 0; break; }
        }
        g_mode = ok;
    }
}

// ---------------- K1: scatter-sum + counts (vector RED) ----------------
__global__ void k_scatter(const float* __restrict__ X,
                          const void* __restrict__ Vp,
                          const void* __restrict__ Ep) {
    int gid = blockIdx.x * 256 + threadIdx.x;        // NI*32 threads
    int inc = gid >> 5;
    int q   = gid & 31;
    int v, e;
    if (g_mode) {
        v = (int)((const long long*)Vp)[inc];
        e = (int)((const long long*)Ep)[inc];
    } else {
        v = ((const int*)Vp)[inc];
        e = ((const int*)Ep)[inc];
    }
    float4 f = *(const float4*)(X + v * D + q * 4);
    float* dst = g_eSum + e * D + q * 4;
    asm volatile("red.global.add.v4.f32 [%0], {%1, %2, %3, %4};"
                 :: "l"(dst), "f"(f.x), "f"(f.y), "f"(f.z), "f"(f.w) : "memory");
    if (q == 0)
        asm volatile("red.global.add.f32 [%0], %1;"
                     :: "l"(&g_eCnt[e]), "f"(1.0f) : "memory");
}

// ---------------- K2: fused GEMM for hX and hEb ----------------
// Rows 0..511   : A = X,                out g_hX  = X @ W1[:, :128].T
// Rows 512..1023: A = eSum/max(cnt,1),  out g_hEb = eX @ W1[:, 128:].T + b1
__global__ void __launch_bounds__(256) k_gemm(const float* __restrict__ X,
                                              const float* __restrict__ W1,
                                              const float* __restrict__ b1) {
    __shared__ float sA[32 * 36];   // [k][row], ld=36
    __shared__ float sB[32 * 68];   // [k][h],  ld=68
    int tid = threadIdx.x;
    int tx = tid & 15, ty = tid >> 4;
    int h0 = blockIdx.x * 64;
    int r0 = blockIdx.y * 32;
    bool isX = (r0 < NN);
    int koff = isX ? 0 : D;

    float acc[2][4];
    #pragma unroll
    for (int i = 0; i < 2; i++)
        #pragma unroll
        for (int j = 0; j < 4; j++) acc[i][j] = 0.0f;

    for (int k0 = 0; k0 < D; k0 += 32) {
        __syncthreads();
        {   // A: 32 rows x 32 k = 256 float4
            int kq = tid & 7;
            int r  = tid >> 3;
            int gr = r0 + r;
            float4 f;
            if (isX) {
                f = *(const float4*)(X + gr * D + k0 + kq * 4);
            } else {
                f = *(const float4*)(g_eSum + (gr - NN) * D + k0 + kq * 4);
                float c = g_eCnt[gr - NN];
                float s = 1.0f / fmaxf(c, 1.0f);
                f.x *= s; f.y *= s; f.z *= s; f.w *= s;
            }
            sA[(kq * 4 + 0) * 36 + r] = f.x;
            sA[(kq * 4 + 1) * 36 + r] = f.y;
            sA[(kq * 4 + 2) * 36 + r] = f.z;
            sA[(kq * 4 + 3) * 36 + r] = f.w;
        }
        #pragma unroll
        for (int i = 0; i < 2; i++) {  // B: 64 h x 32 k = 512 float4
            int lin = tid + 256 * i;
            int kq = lin & 7;
            int hr = lin >> 3;
            float4 g = *(const float4*)(W1 + (h0 + hr) * (2 * D) + koff + k0 + kq * 4);
            sB[(kq * 4 + 0) * 68 + hr] = g.x;
            sB[(kq * 4 + 1) * 68 + hr] = g.y;
            sB[(kq * 4 + 2) * 68 + hr] = g.z;
            sB[(kq * 4 + 3) * 68 + hr] = g.w;
        }
        __syncthreads();

        #pragma unroll
        for (int kk = 0; kk < 32; kk++) {
            float2 a2 = *(float2*)&sA[kk * 36 + 2 * ty];
            float4 b4 = *(float4*)&sB[kk * 68 + 4 * tx];
            float a[2] = {a2.x, a2.y};
            float b[4] = {b4.x, b4.y, b4.z, b4.w};
            #pragma unroll
            for (int i = 0; i < 2; i++)
                #pragma unroll
                for (int j = 0; j < 4; j++)
                    acc[i][j] = fmaf(a[i], b[j], acc[i][j]);
        }
    }

    #pragma unroll
    for (int i = 0; i < 2; i++) {
        int gr = r0 + 2 * ty + i;
        #pragma unroll
        for (int j = 0; j < 4; j++) {
            int h = h0 + 4 * tx + j;
            if (isX) g_hX[gr * H + h] = acc[i][j];
            else     g_hEb[(gr - NN) * H + h] = acc[i][j] + b1[h];
        }
    }
}

// ---------------- K3: fused relu-dot + sigmoid epilogue ----------------
// out[n,m] = clip(sigmoid( sum_h relu(hX[n,h]+hEb[m,h]) * W2[h] + b2 ))
// CTA tile 16n x 32m, 128 threads (4 warps), thread tile 2n x 2m, full h in
// 4 chunks of 64. Grid (16, 32) = 512 CTAs -> ~3.5 CTAs/SM, 2048 warps.
__global__ void __launch_bounds__(128) k_epi(const float* __restrict__ W2,
                                             const float* __restrict__ b2,
                                             float* __restrict__ out) {
    __shared__ float sX[16 * 68];   // [n][h-chunk], ld=68
    __shared__ float sE[32 * 68];   // [m][h-chunk]
    __shared__ float sW[64];
    int tid = threadIdx.x;
    int tx = tid & 15;              // m = m0 + tx + 16j
    int ty = tid >> 4;              // n = n0 + ty + 8i   (ty 0..7)
    int m0 = blockIdx.x * 32;
    int n0 = blockIdx.y * 16;

    ull acc[2][2];
    #pragma unroll
    for (int i = 0; i < 2; i++)
        #pragma unroll
        for (int j = 0; j < 2; j++) acc[i][j] = 0ULL;

    int xoff[2], eoff[2];
    #pragma unroll
    for (int i = 0; i < 2; i++) xoff[i] = (ty + 8 * i) * 68;
    #pragma unroll
    for (int j = 0; j < 2; j++) eoff[j] = (tx + 16 * j) * 68;

    float4 pX[2], pE[4], pW;

    // gmem prefetch of chunk hc into registers
    #define GLOAD(hc)                                                            \
        do {                                                                     \
            _Pragma("unroll")                                                    \
            for (int i_ = 0; i_ < 2; i_++) {          /* 16 rows x 16 quads */   \
                int lin = tid + 128 * i_;                                        \
                int q = lin & 15, r = lin >> 4;       /* r 0..15 */              \
                pX[i_] = *(const float4*)(g_hX + (n0 + r) * H + (hc) + 4 * q);   \
            }                                                                    \
            _Pragma("unroll")                                                    \
            for (int i_ = 0; i_ < 4; i_++) {          /* 32 rows x 16 quads */   \
                int lin = tid + 128 * i_;                                        \
                int q = lin & 15, r = lin >> 4;       /* r 0..31 */              \
                pE[i_] = *(const float4*)(g_hEb + (m0 + r) * H + (hc) + 4 * q);  \
            }                                                                    \
            if (tid < 16) pW = *(const float4*)(W2 + (hc) + 4 * tid);            \
        } while (0)

    #define GSTORE()                                                             \
        do {                                                                     \
            _Pragma("unroll")                                                    \
            for (int i_ = 0; i_ < 2; i_++) {                                     \
                int lin = tid + 128 * i_;                                        \
                int q = lin & 15, r = lin >> 4;                                  \
                *(float4*)&sX[r * 68 + 4 * q] = pX[i_];                          \
            }                                                                    \
            _Pragma("unroll")                                                    \
            for (int i_ = 0; i_ < 4; i_++) {                                     \
                int lin = tid + 128 * i_;                                        \
                int q = lin & 15, r = lin >> 4;                                  \
                *(float4*)&sE[r * 68 + 4 * q] = pE[i_];                          \
            }                                                                    \
            if (tid < 16) *(float4*)&sW[4 * tid] = pW;                           \
        } while (0)

    ulonglong2 Wb[2], Xb[2][2], Eb[2][2];
    #define LOADI(s, h)                                                          \
        do {                                                                     \
            Wb[s] = *(const ulonglong2*)&sW[(h)];                                \
            _Pragma("unroll")                                                    \
            for (int i_ = 0; i_ < 2; i_++)                                       \
                Xb[s][i_] = *(const ulonglong2*)&sX[xoff[i_] + (h)];             \
            _Pragma("unroll")                                                    \
            for (int j_ = 0; j_ < 2; j_++)                                       \
                Eb[s][j_] = *(const ulonglong2*)&sE[eoff[j_] + (h)];             \
        } while (0)
    #define COMP(s)                                                              \
        do {                                                                     \
            _Pragma("unroll")                                                    \
            for (int i_ = 0; i_ < 2; i_++)                                       \
                _Pragma("unroll")                                                \
                for (int j_ = 0; j_ < 2; j_++) {                                 \
                    triad(acc[i_][j_], Xb[s][i_].x, Eb[s][j_].x, Wb[s].x);       \
                    triad(acc[i_][j_], Xb[s][i_].y, Eb[s][j_].y, Wb[s].y);       \
                }                                                                \
        } while (0)

    GLOAD(0);
    GSTORE();
    __syncthreads();

    #pragma unroll 1
    for (int c = 0; c < 4; c++) {
        if (c < 3) GLOAD(64 * (c + 1));       // prefetch next chunk
        LOADI(0, 0);
        #pragma unroll
        for (int it = 0; it < 16; it++) {
            if (it < 15) {
                if (it & 1) LOADI(0, 4 * (it + 1));
                else        LOADI(1, 4 * (it + 1));
            }
            if (it & 1) COMP(1);
            else        COMP(0);
        }
        if (c < 3) {
            __syncthreads();
            GSTORE();
            __syncthreads();
        }
    }
    #undef GLOAD
    #undef GSTORE
    #undef LOADI
    #undef COMP

    // direct sigmoid + clip + store (2 rows x 16 cols per (i,j): coalesced 64B segs)
    float b2v = b2[0];
    #pragma unroll
    for (int i = 0; i < 2; i++) {
        int n = n0 + ty + 8 * i;
        #pragma unroll
        for (int j = 0; j < 2; j++) {
            int m = m0 + tx + 16 * j;
            float lg = hsum2(acc[i][j]) + b2v;
            float p = 1.0f / (1.0f + __expf(-lg));
            p = fminf(fmaxf(p, 1e-6f), 1.0f - 1e-6f);
            out[n * NE + m] = p;
        }
    }
}

// ---------------- launch ----------------
extern "C" void kernel_launch(void* const* d_in, const int* in_sizes, int n_in,
                              void* d_out, int out_size) {
    const float* X  = (const float*)d_in[0];
    const void*  V  = d_in[1];
    const void*  E  = d_in[2];
    const float* W1 = (const float*)d_in[3];
    const float* b1 = (const float*)d_in[4];
    const float* W2 = (const float*)d_in[5];
    const float* b2 = (const float*)d_in[6];
    float* out = (float*)d_out;

    k_zero_detect<<<65, 256>>>(E);                             // 16512 float4 + detect
    k_scatter<<<(NI * 32) / 256, 256>>>(X, V, E);              // 1024 blocks
    k_gemm<<<dim3(H / 64, (NN + NE) / 32), 256>>>(X, W1, b1);  // (4,32) = 128 CTAs
    k_epi<<<dim3(NE / 32, NN / 16), 128>>>(W2, b2, out);       // (16,32) = 512 CTAs
}